// round 3
// baseline (speedup 1.0000x reference)
#include <cuda_runtime.h>

#define NP 300000
#define NC 10000

// ---- scratch (device globals; no allocations allowed) ----
__device__ int g_count[NC];
__device__ int g_offsets[NC + 1];
__device__ int g_cursor[NC];
__device__ int g_order[NP];
__device__ int g_is64;

// ---------------------------------------------------------------------------
// Detect whether index arrays are int64 (odd 32-bit words all zero) or int32.
// ---------------------------------------------------------------------------
__global__ void detect_kernel(const int* __restrict__ sp) {
    __shared__ int any;
    if (threadIdx.x == 0) any = 0;
    __syncthreads();
    int v = 0;
    for (int i = threadIdx.x; i < 2048; i += blockDim.x)
        v |= sp[2 * i + 1];
    if (v) atomicOr(&any, 1);
    __syncthreads();
    if (threadIdx.x == 0) g_is64 = any ? 0 : 1;
}

__global__ void zero_kernel() {
    int i = blockIdx.x * blockDim.x + threadIdx.x;
    if (i < NC) g_count[i] = 0;
}

__global__ void hist_kernel(const int* __restrict__ dens) {
    int p = blockIdx.x * blockDim.x + threadIdx.x;
    if (p < NP) {
        int st = g_is64 ? 2 : 1;
        atomicAdd(&g_count[dens[p * st]], 1);
    }
}

// Single-block exclusive scan over 10k counts (1024 threads x 10 each).
__global__ void scan_kernel() {
    __shared__ int part[1024];
    int t = threadIdx.x;
    const int PER = (NC + 1023) / 1024;  // 10
    int base = t * PER;
    int sum = 0;
#pragma unroll
    for (int k = 0; k < PER; k++) {
        int i = base + k;
        if (i < NC) sum += g_count[i];
    }
    part[t] = sum;
    __syncthreads();
    // inclusive Hillis-Steele scan
    for (int off = 1; off < 1024; off <<= 1) {
        int v = part[t];
        int add = (t >= off) ? part[t - off] : 0;
        __syncthreads();
        part[t] = v + add;
        __syncthreads();
    }
    int run = (t == 0) ? 0 : part[t - 1];
#pragma unroll
    for (int k = 0; k < PER; k++) {
        int i = base + k;
        if (i < NC) {
            g_offsets[i] = run;
            g_cursor[i] = run;
            run += g_count[i];
        }
    }
    if (t == 1023) g_offsets[NC] = part[1023];
}

__global__ void scatter_kernel(const int* __restrict__ dens) {
    int p = blockIdx.x * blockDim.x + threadIdx.x;
    if (p < NP) {
        int st = g_is64 ? 2 : 1;
        int c = dens[p * st];
        int pos = atomicAdd(&g_cursor[c], 1);
        g_order[pos] = p;
    }
}

// ---------------------------------------------------------------------------
// Main kernel: one CTA per center. 80 float4 slots cover the 320-float row
// (l0: slots 0-4, l1: 5-19, l2: 20-44, l3: 45-79). Threads 0-239 form 3
// groups of 80 processing 3 pairs concurrently; per-species accumulation in
// registers (predicated adds), then W-combine + coalesced store.
//
// Output per center (1280 floats): for l in 0..3, index (c*4+d)*20+n,
// value = sum_s W[d*4+s] * S[s][off_in_l + c*20 + n].
// ---------------------------------------------------------------------------
__global__ __launch_bounds__(256) void main_kernel(
    const float4* __restrict__ v0, const float4* __restrict__ v1,
    const float4* __restrict__ v2, const float4* __restrict__ v3,
    const float* __restrict__ W, const int* __restrict__ sp,
    float* __restrict__ out) {
    __shared__ float acc[12 * 320];  // [group][species][320] as floats
    __shared__ float sW[16];
    int tid = threadIdx.x;
    if (tid < 16) sW[tid] = W[tid];
    int center = blockIdx.x;
    int start = g_offsets[center];
    int end = g_offsets[center + 1];
    int sstride = g_is64 ? 2 : 1;

    int g = tid / 80;
    int slot = tid - g * 80;
    if (g < 3) {
        const float4* base;
        int rowf4, loc;
        if (slot < 5)       { base = v0; rowf4 = 5;  loc = slot; }
        else if (slot < 20) { base = v1; rowf4 = 15; loc = slot - 5; }
        else if (slot < 45) { base = v2; rowf4 = 25; loc = slot - 20; }
        else                { base = v3; rowf4 = 35; loc = slot - 45; }

        float4 r[4];
#pragma unroll
        for (int s = 0; s < 4; s++) r[s] = make_float4(0.f, 0.f, 0.f, 0.f);

        for (int j = start + g; j < end; j += 3) {
            int p = g_order[j];
            int s = sp[p * sstride];
            float4 v = __ldg(base + (size_t)p * rowf4 + loc);
#pragma unroll
            for (int k = 0; k < 4; k++) {
                if (s == k) {
                    r[k].x += v.x; r[k].y += v.y;
                    r[k].z += v.z; r[k].w += v.w;
                }
            }
        }
        float4* accv = (float4*)acc;
#pragma unroll
        for (int s = 0; s < 4; s++)
            accv[(g * 4 + s) * 80 + slot] = r[s];
    }
    __syncthreads();

    float* outc = out + (size_t)center * 1280;
    for (int o = tid; o < 1280; o += 256) {
        int l = (o >= 80) + (o >= 320) + (o >= 720);
        int off_out = (l == 0) ? 0 : (l == 1) ? 80 : (l == 2) ? 320 : 720;
        int off_in  = (l == 0) ? 0 : (l == 1) ? 20 : (l == 2) ? 80 : 180;
        int i = o - off_out;
        int n = i % 20;
        int d = (i / 20) & 3;
        int c = i / 80;
        int e = off_in + c * 20 + n;
        float sum = 0.f;
#pragma unroll
        for (int s = 0; s < 4; s++) {
            float a = acc[s * 320 + e] + acc[(4 + s) * 320 + e] +
                      acc[(8 + s) * 320 + e];
            sum = fmaf(sW[d * 4 + s], a, sum);
        }
        outc[o] = sum;
    }
}

extern "C" void kernel_launch(void* const* d_in, const int* in_sizes, int n_in,
                              void* d_out, int out_size) {
    const float4* v0 = (const float4*)d_in[0];
    const float4* v1 = (const float4*)d_in[1];
    const float4* v2 = (const float4*)d_in[2];
    const float4* v3 = (const float4*)d_in[3];
    const float* W = (const float*)d_in[4];
    const int* sp = (const int*)d_in[5];
    const int* dens = (const int*)d_in[6];
    float* out = (float*)d_out;

    detect_kernel<<<1, 256>>>(sp);
    zero_kernel<<<(NC + 255) / 256, 256>>>();
    hist_kernel<<<(NP + 255) / 256, 256>>>(dens);
    scan_kernel<<<1, 1024>>>();
    scatter_kernel<<<(NP + 255) / 256, 256>>>(dens);
    main_kernel<<<NC, 256>>>(v0, v1, v2, v3, W, sp, out);
}

// round 4
// speedup vs baseline: 1.1138x; 1.1138x over previous
#include <cuda_runtime.h>

#define NP 300000
#define NC 10000

// ---- scratch (device globals; no allocations allowed) ----
__device__ int g_count[NC];
__device__ int g_offsets[NC + 1];
__device__ int g_cursor[NC];
__device__ unsigned g_order[NP];   // packed: (pair_index << 2) | species
__device__ int g_is64;

// ---------------------------------------------------------------------------
// Zero histogram + detect int64-vs-int32 indices (block 0 samples odd words).
// ---------------------------------------------------------------------------
__global__ void zero_detect_kernel(const int* __restrict__ sp) {
    int i = blockIdx.x * blockDim.x + threadIdx.x;
    if (i < NC) g_count[i] = 0;
    if (blockIdx.x == 0) {
        __shared__ int any;
        if (threadIdx.x == 0) any = 0;
        __syncthreads();
        int v = 0;
        for (int k = threadIdx.x; k < 2048; k += blockDim.x)
            v |= sp[2 * k + 1];
        if (v) atomicOr(&any, 1);
        __syncthreads();
        if (threadIdx.x == 0) g_is64 = any ? 0 : 1;
    }
}

__global__ void hist_kernel(const int* __restrict__ dens) {
    int p = blockIdx.x * blockDim.x + threadIdx.x;
    if (p < NP) {
        int st = g_is64 ? 2 : 1;
        atomicAdd(&g_count[dens[p * st]], 1);
    }
}

// ---------------------------------------------------------------------------
// Single-block exclusive scan over 10k counts. Coalesced smem staging +
// warp-shuffle scan (2 barriers for the scan itself).
// ---------------------------------------------------------------------------
__global__ __launch_bounds__(1024) void scan_kernel() {
    __shared__ int sc[NC];     // staged counts, later overwritten with offsets
    __shared__ int wsum[32];
    int t = threadIdx.x;
    // coalesced load of counts
    for (int i = t; i < NC; i += 1024) sc[i] = g_count[i];
    __syncthreads();

    const int PER = (NC + 1023) / 1024;  // 10
    int base = t * PER;
    int local[PER];
    int sum = 0;
#pragma unroll
    for (int k = 0; k < PER; k++) {
        int i = base + k;
        int c = (i < NC) ? sc[i] : 0;
        local[k] = c;
        sum += c;
    }
    int lane = t & 31, warp = t >> 5;
    int inc = sum;
#pragma unroll
    for (int off = 1; off < 32; off <<= 1) {
        int n = __shfl_up_sync(0xffffffffu, inc, off);
        if (lane >= off) inc += n;
    }
    if (lane == 31) wsum[warp] = inc;
    __syncthreads();
    if (warp == 0) {
        int v = wsum[lane];
#pragma unroll
        for (int off = 1; off < 32; off <<= 1) {
            int n = __shfl_up_sync(0xffffffffu, v, off);
            if (lane >= off) v += n;
        }
        wsum[lane] = v;
    }
    __syncthreads();
    int run = inc - sum + (warp ? wsum[warp - 1] : 0);  // exclusive prefix
#pragma unroll
    for (int k = 0; k < PER; k++) {
        int i = base + k;
        if (i < NC) {
            sc[i] = run;
            run += local[k];
        }
    }
    __syncthreads();
    // coalesced store of offsets + cursor copy
    for (int i = t; i < NC; i += 1024) {
        int o = sc[i];
        g_offsets[i] = o;
        g_cursor[i] = o;
    }
    if (t == 1023) g_offsets[NC] = run;  // thread 1023 owns the final run total
}

// ---------------------------------------------------------------------------
// Scatter pair ids, packing species into the low 2 bits so the main kernel's
// dependent-load chain is order -> vec (2 levels instead of 3).
// ---------------------------------------------------------------------------
__global__ void scatter_kernel(const int* __restrict__ dens,
                               const int* __restrict__ sp) {
    int p = blockIdx.x * blockDim.x + threadIdx.x;
    if (p < NP) {
        int st = g_is64 ? 2 : 1;
        int c = dens[p * st];
        int s = sp[p * st] & 3;
        int pos = atomicAdd(&g_cursor[c], 1);
        g_order[pos] = ((unsigned)p << 2) | (unsigned)s;
    }
}

// ---------------------------------------------------------------------------
// Main kernel: one CTA per center, 320 threads = 4 groups of 80. Each group's
// 80 float4 slots cover the 320-float pair row (l0: 0-4, l1: 5-19, l2: 20-44,
// l3: 45-79). Groups take contiguous quarters of the center's pair range and
// process 2 pairs per iteration (independent loads -> pipelined). Per-species
// register accumulation (uniform branch on s within a group), then W-combine
// in smem + coalesced store.
// ---------------------------------------------------------------------------
__global__ __launch_bounds__(320) void main_kernel(
    const float4* __restrict__ v0, const float4* __restrict__ v1,
    const float4* __restrict__ v2, const float4* __restrict__ v3,
    const float* __restrict__ W, float* __restrict__ out) {
    __shared__ float acc[16 * 320];  // [group*4+species][320]
    __shared__ float sW[16];
    int tid = threadIdx.x;
    if (tid < 16) sW[tid] = W[tid];
    int center = blockIdx.x;
    int start = g_offsets[center];
    int end = g_offsets[center + 1];

    int g = tid / 80;
    int slot = tid - g * 80;

    const float4* base;
    int rowf4, loc;
    if (slot < 5)       { base = v0; rowf4 = 5;  loc = slot; }
    else if (slot < 20) { base = v1; rowf4 = 15; loc = slot - 5; }
    else if (slot < 45) { base = v2; rowf4 = 25; loc = slot - 20; }
    else                { base = v3; rowf4 = 35; loc = slot - 45; }

    float4 r[4];
#pragma unroll
    for (int s = 0; s < 4; s++) r[s] = make_float4(0.f, 0.f, 0.f, 0.f);

    // contiguous per-group range
    int len = end - start;
    int q = len >> 2, rem = len & 3;
    int b0 = start + g * q + min(g, rem);
    int b1 = b0 + q + (g < rem ? 1 : 0);

    int j = b0;
    for (; j + 1 < b1; j += 2) {
        unsigned e0 = g_order[j];
        unsigned e1 = g_order[j + 1];
        float4 va = __ldg(base + (size_t)(e0 >> 2) * rowf4 + loc);
        float4 vb = __ldg(base + (size_t)(e1 >> 2) * rowf4 + loc);
        int s0 = e0 & 3, s1 = e1 & 3;
#pragma unroll
        for (int k = 0; k < 4; k++) {
            if (s0 == k) {
                r[k].x += va.x; r[k].y += va.y;
                r[k].z += va.z; r[k].w += va.w;
            }
        }
#pragma unroll
        for (int k = 0; k < 4; k++) {
            if (s1 == k) {
                r[k].x += vb.x; r[k].y += vb.y;
                r[k].z += vb.z; r[k].w += vb.w;
            }
        }
    }
    if (j < b1) {
        unsigned e0 = g_order[j];
        float4 va = __ldg(base + (size_t)(e0 >> 2) * rowf4 + loc);
        int s0 = e0 & 3;
#pragma unroll
        for (int k = 0; k < 4; k++) {
            if (s0 == k) {
                r[k].x += va.x; r[k].y += va.y;
                r[k].z += va.z; r[k].w += va.w;
            }
        }
    }

    float4* accv = (float4*)acc;
#pragma unroll
    for (int s = 0; s < 4; s++)
        accv[(g * 4 + s) * 80 + slot] = r[s];
    __syncthreads();

    // W-combine + coalesced store: 1280 outputs, 4 per thread.
    float* outc = out + (size_t)center * 1280;
    for (int o = tid; o < 1280; o += 320) {
        int l = (o >= 80) + (o >= 320) + (o >= 720);
        int off_out = (l == 0) ? 0 : (l == 1) ? 80 : (l == 2) ? 320 : 720;
        int off_in  = (l == 0) ? 0 : (l == 1) ? 20 : (l == 2) ? 80 : 180;
        int i = o - off_out;
        int n = i % 20;
        int d = (i / 20) & 3;
        int c = i / 80;
        int e = off_in + c * 20 + n;
        float sum = 0.f;
#pragma unroll
        for (int s = 0; s < 4; s++) {
            float a = acc[s * 320 + e] + acc[(4 + s) * 320 + e] +
                      acc[(8 + s) * 320 + e] + acc[(12 + s) * 320 + e];
            sum = fmaf(sW[d * 4 + s], a, sum);
        }
        outc[o] = sum;
    }
}

extern "C" void kernel_launch(void* const* d_in, const int* in_sizes, int n_in,
                              void* d_out, int out_size) {
    const float4* v0 = (const float4*)d_in[0];
    const float4* v1 = (const float4*)d_in[1];
    const float4* v2 = (const float4*)d_in[2];
    const float4* v3 = (const float4*)d_in[3];
    const float* W = (const float*)d_in[4];
    const int* sp = (const int*)d_in[5];
    const int* dens = (const int*)d_in[6];
    float* out = (float*)d_out;

    zero_detect_kernel<<<(NC + 255) / 256, 256>>>(sp);
    hist_kernel<<<(NP + 255) / 256, 256>>>(dens);
    scan_kernel<<<1, 1024>>>();
    scatter_kernel<<<(NP + 255) / 256, 256>>>(dens, sp);
    main_kernel<<<NC, 320>>>(v0, v1, v2, v3, W, out);
}